// round 5
// baseline (speedup 1.0000x reference)
#include <cuda_runtime.h>
#include <math.h>

#define STEPS 2048
#define BATCH 512
#define SPB   4
#define NBLK  (BATCH / SPB)   // 128 blocks -> one wave
#define THREADS 512

typedef unsigned long long u64;

__device__ float g_baseflow[BATCH];

// ---------------------------------------------------------------------------
__device__ __forceinline__ u64 pack2(float lo, float hi) {
    u64 r; asm("mov.b64 %0, {%1, %2};" : "=l"(r) : "f"(lo), "f"(hi)); return r;
}
__device__ __forceinline__ void unpack2(u64 v, float& lo, float& hi) {
    asm("mov.b64 {%0, %1}, %2;" : "=f"(lo), "=f"(hi) : "l"(v));
}
__device__ __forceinline__ void fma2(u64& acc, u64 a, u64 b) {
    asm("fma.rn.f32x2 %0, %1, %2, %0;" : "+l"(acc) : "l"(a), "l"(b));
}
__device__ __forceinline__ float fast_sigmoid(float v) {
    return __fdividef(1.0f, 1.0f + __expf(-v));
}

// ---------------------------------------------------------------------------
// Kernel 1: per-batch-element 25th percentile of flow (bitonic sort)
// ---------------------------------------------------------------------------
__global__ void baseflow_kernel(const float* __restrict__ hyd) {
    __shared__ float v[STEPS];
    const int b = blockIdx.x;
    const int tid = threadIdx.x;
    for (int t = tid; t < STEPS; t += blockDim.x)
        v[t] = hyd[(t * BATCH + b) * 17];
    __syncthreads();
    for (int k = 2; k <= STEPS; k <<= 1) {
        for (int j = k >> 1; j > 0; j >>= 1) {
            for (int i = tid; i < STEPS; i += blockDim.x) {
                int l = i ^ j;
                if (l > i) {
                    float a = v[i], c = v[l];
                    bool up = ((i & k) == 0);
                    if ((a > c) == up) { v[i] = c; v[l] = a; }
                }
            }
            __syncthreads();
        }
    }
    if (tid == 0)
        g_baseflow[b] = 0.25f * v[511] + 0.75f * v[512];   // pos = 511.75
}

// ---------------------------------------------------------------------------
struct __align__(16) Smem {
    float w0t[16 * 128];     // W0 x-part transposed [i][j]
    float w0sp[8 * 128];     // 0.01 * W0 stores-part [k][j]
    float b0s[128];
    float b1s[128];
    float bcs[96];
    float xin[16 * 4];       // next-step x [i][s]
    float l0p[128 * 4];      // layer0-x partial incl b0 [j*4+s]
    float hA[128 * 4];       // layer0 out [j*4+s]
    float hB[128 * 4];       // layer1 out
    float part[4][128][4];   // reduction partials [q][j][s]
    float outg[4][80];       // sigmoided gates [s][col]
    float st[4 * 8];         // stores (scratch for broadcast in epilogue)
    float bflow_s[4];
};

// ---------------------------------------------------------------------------
// 512 threads = 16 warps (4/SMSP). j = tid&127 owns unit j; q = tid>>7 owns a
// 32-slice of the reduction dim. 4 barriers per step:
//   S1: layer1 partials (+ LDG prefetch x_{t+1}, rain_{t+1})
//   S2: combine1 -> hB (+ stage x_{t+1} into xin)
//   S3: layer2 partials (j<89)  ||  warps 3/7/11/15: l0x(t+1) -> l0p
//   S4: warps 0-3: combine2+sigmoid+softmax+serial tail+hA(t+1) finish
// ---------------------------------------------------------------------------
__global__ void __launch_bounds__(THREADS, 1)
hyd_kernel(const float* __restrict__ hyd,
           const float* __restrict__ W0, const float* __restrict__ b0,
           const float* __restrict__ W1, const float* __restrict__ b1,
           const float* __restrict__ Wi, const float* __restrict__ bi,
           const float* __restrict__ Wo, const float* __restrict__ bo,
           float* __restrict__ out)
{
    __shared__ Smem S;
    const int tid   = threadIdx.x;
    const int j     = tid & 127;
    const int q     = tid >> 7;
    const int lane  = tid & 31;
    const int wwarp = tid >> 5;         // 0..15
    const int blk   = blockIdx.x;

    // ---- register-resident weight slices ----
    float w1r[32], wcr[32];
    #pragma unroll
    for (int k = 0; k < 32; k++) w1r[k] = W1[j * 128 + q * 32 + k];
    if (j < 9) {
        #pragma unroll
        for (int k = 0; k < 32; k++) wcr[k] = Wi[j * 128 + q * 32 + k];
    } else if (j < 89) {
        #pragma unroll
        for (int k = 0; k < 32; k++) wcr[k] = Wo[(j - 9) * 128 + q * 32 + k];
    } else {
        #pragma unroll
        for (int k = 0; k < 32; k++) wcr[k] = 0.f;
    }

    // ---- SMEM init ----
    for (int idx = tid; idx < 16 * 128; idx += THREADS) {
        int i = idx >> 7, jj = idx & 127;
        S.w0t[idx] = W0[jj * 24 + i];
    }
    for (int idx = tid; idx < 8 * 128; idx += THREADS) {
        int k = idx >> 7, jj = idx & 127;
        S.w0sp[idx] = 0.01f * W0[jj * 24 + 16 + k];
    }
    if (tid < 128) { S.b0s[tid] = b0[tid]; S.b1s[tid] = b1[tid]; }
    if (tid < 89)  S.bcs[tid] = (tid < 9) ? bi[tid] : bo[tid - 9];
    if (tid < 32)  S.st[tid] = ((tid & 7) == 1) ? 1.0f : 0.0f;
    if (tid < SPB) S.bflow_s[tid] = g_baseflow[blk * SPB + tid];

    // per-warp roles
    const int bsample = blk * SPB + wwarp;          // warps 0-3: epilogue sample
    const int xsample = blk * SPB + (wwarp - 4);    // warps 4-7: x prefetch sample
    float rain_cur = 0.f, rain_next = 0.f, xreg = 0.f;

    if (wwarp < 4 && lane == 0)
        rain_cur = hyd[bsample * 17 + 1];           // x_0[rain]
    if (wwarp >= 4 && wwarp < 8 && lane < 16)
        S.xin[lane * 4 + (wwarp - 4)] = hyd[xsample * 17 + 1 + lane];  // x_0
    __syncthreads();

    // ---- bootstrap: l0x(0) ----
    if ((wwarp & 3) == 3) {
        int jj = (tid >> 7) * 32 + lane;
        float bj = S.b0s[jj];
        u64 a01 = pack2(bj, bj), a23 = a01;
        #pragma unroll
        for (int i = 0; i < 16; i++) {
            float w = S.w0t[i * 128 + jj];
            u64 wd = pack2(w, w);
            ulonglong2 h = *(const ulonglong2*)&S.xin[i * 4];
            fma2(a01, h.x, wd); fma2(a23, h.y, wd);
        }
        ulonglong2 pv; pv.x = a01; pv.y = a23;
        *(ulonglong2*)&S.l0p[jj * 4] = pv;
    }
    __syncthreads();

    // ---- bootstrap: hA(0) ----
    {
        int jj = tid >> 2, s = tid & 3;
        float v = S.l0p[jj * 4 + s];
        #pragma unroll
        for (int k = 0; k < 8; k++)
            v = fmaf(S.w0sp[k * 128 + jj], S.st[s * 8 + k], v);
        S.hA[jj * 4 + s] = fmaxf(v, 0.f);
    }
    __syncthreads();

    // persistent stores state in lane 0 of warps 0-3
    float sv[8];
    #pragma unroll
    for (int k = 0; k < 8; k++) sv[k] = (k == 1) ? 1.0f : 0.0f;

    for (int t = 0; t < STEPS; t++) {
        // ======== S1: layer1 partials ========
        {
            float bj = (q == 0) ? S.b1s[j] : 0.f;
            u64 a01 = pack2(bj, bj), a23 = a01;
            const float* hp = &S.hA[q * 128];
            #pragma unroll
            for (int k = 0; k < 32; k++) {
                u64 wd = pack2(w1r[k], w1r[k]);
                ulonglong2 h = *(const ulonglong2*)&hp[k * 4];
                fma2(a01, h.x, wd); fma2(a23, h.y, wd);
            }
            ulonglong2 pv; pv.x = a01; pv.y = a23;
            *(ulonglong2*)&S.part[q][j][0] = pv;
        }
        // prefetch x_{t+1} / rain_{t+1}
        if (t + 1 < STEPS) {
            if (wwarp < 4 && lane == 0)
                rain_next = hyd[((t + 1) * BATCH + bsample) * 17 + 1];
            if (wwarp >= 4 && wwarp < 8 && lane < 16)
                xreg = hyd[((t + 1) * BATCH + xsample) * 17 + 1 + lane];
        }
        __syncthreads();

        // ======== S2: combine1 -> hB ; stage x_{t+1} ========
        {
            int jj = tid >> 2, s = tid & 3;
            float v = S.part[0][jj][s] + S.part[1][jj][s]
                    + S.part[2][jj][s] + S.part[3][jj][s];
            S.hB[jj * 4 + s] = fmaxf(v, 0.f);
        }
        if (wwarp >= 4 && wwarp < 8 && lane < 16)
            S.xin[lane * 4 + (wwarp - 4)] = xreg;
        __syncthreads();

        // ======== S3: layer2 partials || l0x(t+1) ========
        if ((wwarp & 3) == 3) {
            // warps 3,7,11,15 (j>=96, idle for layer2): layer0 x-part for t+1
            int jj = (tid >> 7) * 32 + lane;
            float bj = S.b0s[jj];
            u64 a01 = pack2(bj, bj), a23 = a01;
            #pragma unroll
            for (int i = 0; i < 16; i++) {
                float w = S.w0t[i * 128 + jj];
                u64 wd = pack2(w, w);
                ulonglong2 h = *(const ulonglong2*)&S.xin[i * 4];
                fma2(a01, h.x, wd); fma2(a23, h.y, wd);
            }
            ulonglong2 pv; pv.x = a01; pv.y = a23;
            *(ulonglong2*)&S.l0p[jj * 4] = pv;
        } else if (j < 89) {
            float bj = (q == 0) ? S.bcs[j] : 0.f;
            u64 a01 = pack2(bj, bj), a23 = a01;
            const float* hp = &S.hB[q * 128];
            #pragma unroll
            for (int k = 0; k < 32; k++) {
                u64 wd = pack2(wcr[k], wcr[k]);
                ulonglong2 h = *(const ulonglong2*)&hp[k * 4];
                fma2(a01, h.x, wd); fma2(a23, h.y, wd);
            }
            ulonglong2 pv; pv.x = a01; pv.y = a23;
            *(ulonglong2*)&S.part[q][j][0] = pv;
        }
        __syncthreads();

        // ======== S4: epilogue (warps 0-3, sample = wwarp) + hA(t+1) ========
        if (wwarp < 4) {
            const int s = wwarp;
            // combine2 for this sample
            float v0 = S.part[0][lane][s] + S.part[1][lane][s]
                     + S.part[2][lane][s] + S.part[3][lane][s];
            int j1 = lane + 32;
            float v1 = S.part[0][j1][s] + S.part[1][j1][s]
                     + S.part[2][j1][s] + S.part[3][j1][s];
            float v2 = 0.f;
            int j2 = lane + 64;
            if (lane < 25)
                v2 = S.part[0][j2][s] + S.part[1][j2][s]
                   + S.part[2][j2][s] + S.part[3][j2][s];

            // sigmoids -> outg (gate col = j-9)
            if (lane >= 9) S.outg[s][lane - 9] = fast_sigmoid(v0);
            S.outg[s][lane + 23] = fast_sigmoid(v1);
            if (lane < 25) S.outg[s][lane + 55] = fast_sigmoid(v2);

            // softmax over 9 logits (16-wide reductions)
            float logit = (lane < 9) ? v0 : -1e30f;
            float m = logit;
            #pragma unroll
            for (int off = 8; off > 0; off >>= 1)
                m = fmaxf(m, __shfl_xor_sync(0xffffffffu, m, off, 16));
            float e = (lane < 9) ? __expf(logit - m) : 0.f;
            float ssum = e;
            #pragma unroll
            for (int off = 8; off > 0; off >>= 1)
                ssum += __shfl_xor_sync(0xffffffffu, ssum, off, 16);
            float aval = __fdividef(e, ssum);

            // gather a[1..8] to all lanes (lane0 uses them)
            float ag[8];
            #pragma unroll
            for (int k = 0; k < 8; k++)
                ag[k] = __shfl_sync(0xffffffffu, aval, k + 1);
            __syncwarp();

            if (lane == 0) {
                const float* bb = S.outg[s];
                #pragma unroll
                for (int k = 0; k < 8; k++) sv[k] += ag[k] * rain_cur;
                #pragma unroll
                for (int d = 0; d < 8; d++) {
                    float fb[8]; float fsum = 0.f;
                    #pragma unroll
                    for (int k = 0; k < 8; k++) { fb[k] = bb[d * 8 + k] * sv[k]; fsum += fb[k]; }
                    #pragma unroll
                    for (int k = 0; k < 8; k++) sv[k] -= fb[k];
                    sv[d] += fsum;
                }
                #pragma unroll
                for (int k = 0; k < 8; k++) sv[k] -= bb[64 + k] * sv[k];   // escape
                float flow = 0.f;
                #pragma unroll
                for (int k = 0; k < 8; k++) {
                    float fd = bb[72 + k] * sv[k];
                    flow += fd;
                    sv[k] -= fd;
                }
                out[t * BATCH + bsample] = flow;
                if (t == 0)
                    sv[2] = S.bflow_s[s] / fmaxf(bb[74], 1e-5f);   // b_flow[SLOW]
                // publish stores for hA-finish broadcast
                #pragma unroll
                for (int k = 0; k < 8; k++) S.st[s * 8 + k] = sv[k];
            }
            __syncwarp();

            // hA(t+1) finish: add stores part to l0p, relu
            float stv[8];
            #pragma unroll
            for (int k = 0; k < 8; k++) stv[k] = S.st[s * 8 + k];
            #pragma unroll
            for (int mI = 0; mI < 4; mI++) {
                int jj = lane + 32 * mI;
                float v = S.l0p[jj * 4 + s];
                #pragma unroll
                for (int k = 0; k < 8; k++)
                    v = fmaf(S.w0sp[k * 128 + jj], stv[k], v);
                S.hA[jj * 4 + s] = fmaxf(v, 0.f);
            }
            rain_cur = rain_next;
        }
        __syncthreads();
    }
}

// ---------------------------------------------------------------------------
// Harness entry.  Inputs: hyd_input, W0, b0, W1, b1, W_in, b_in, W_out, b_out
// ---------------------------------------------------------------------------
extern "C" void kernel_launch(void* const* d_in, const int* in_sizes, int n_in,
                              void* d_out, int out_size) {
    const float* hyd = (const float*)d_in[0];
    const float* W0  = (const float*)d_in[1];
    const float* b0  = (const float*)d_in[2];
    const float* W1  = (const float*)d_in[3];
    const float* b1  = (const float*)d_in[4];
    const float* Wi  = (const float*)d_in[5];
    const float* bi  = (const float*)d_in[6];
    const float* Wo  = (const float*)d_in[7];
    const float* bo  = (const float*)d_in[8];
    float* out = (float*)d_out;

    baseflow_kernel<<<BATCH, 1024>>>(hyd);
    hyd_kernel<<<NBLK, THREADS>>>(hyd, W0, b0, W1, b1, Wi, bi, Wo, bo, out);
}

// round 7
// speedup vs baseline: 1.0540x; 1.0540x over previous
#include <cuda_runtime.h>
#include <math.h>

#define STEPS 2048
#define BATCH 512
#define SPB   4
#define NBLK  (BATCH / SPB)   // 128 blocks -> one wave
#define THREADS 512

typedef unsigned long long u64;

__device__ float g_baseflow[BATCH];

// ---------------------------------------------------------------------------
__device__ __forceinline__ u64 pack2(float lo, float hi) {
    u64 r; asm("mov.b64 %0, {%1, %2};" : "=l"(r) : "f"(lo), "f"(hi)); return r;
}
__device__ __forceinline__ void fma2(u64& acc, u64 a, u64 b) {
    asm("fma.rn.f32x2 %0, %1, %2, %0;" : "+l"(acc) : "l"(a), "l"(b));
}
__device__ __forceinline__ float fast_sigmoid(float v) {
    return __fdividef(1.0f, 1.0f + __expf(-v));
}

// ---------------------------------------------------------------------------
// Kernel 1: per-batch-element 25th percentile of flow (bitonic sort)
// ---------------------------------------------------------------------------
__global__ void baseflow_kernel(const float* __restrict__ hyd) {
    __shared__ float v[STEPS];
    const int b = blockIdx.x;
    const int tid = threadIdx.x;
    for (int t = tid; t < STEPS; t += blockDim.x)
        v[t] = hyd[(t * BATCH + b) * 17];
    __syncthreads();
    for (int k = 2; k <= STEPS; k <<= 1) {
        for (int j = k >> 1; j > 0; j >>= 1) {
            for (int i = tid; i < STEPS; i += blockDim.x) {
                int l = i ^ j;
                if (l > i) {
                    float a = v[i], c = v[l];
                    bool up = ((i & k) == 0);
                    if ((a > c) == up) { v[i] = c; v[l] = a; }
                }
            }
            __syncthreads();
        }
    }
    if (tid == 0)
        g_baseflow[b] = 0.25f * v[511] + 0.75f * v[512];   // pos = 511.75
}

// ---------------------------------------------------------------------------
struct __align__(16) Smem {
    float w0t[16 * 128];     // W0 x-part transposed [i][j]
    float w0sp[8 * 128];     // 0.01 * W0 stores-part [k][j]
    float b0s[128];
    float b1s[128];
    float bcs[96];
    float xin[16 * 4];       // staged x_{t+1} [i][s]
    float l0p[128 * 4];      // layer0-x partial incl b0 [j*4+s]
    float hA[128 * 4];       // layer0 out [j*4+s]
    float hB[128 * 4];       // layer1 out
    float part[4][128][4];   // reduction partials [q][j][s]
    float outg[4][80];       // sigmoided gates [s][col]
    float st[4 * 8];         // stores broadcast (epilogue -> hA finish)
    float bflow_s[4];
};

// ---------------------------------------------------------------------------
// 512 threads = 16 warps (4/SMSP). j = tid&127 owns unit j; q = tid>>7 owns a
// 32-slice of the reduction dim. 5 barriers per step:
//   S1: layer1 partials (+ LDG prefetch x_{t+1}, rain_{t+1})
//   S2: combine1 -> hB (all 512) ; stage x_{t+1} -> xin
//   S3: layer2 partials (j<89)  ||  warps 3/7/11/15: l0x(t+1) -> l0p
//   S4: warps 0-3 (warp s = sample s): combine2 + sigmoids + scalar softmax
//       + serial mixing in lane 0 + publish stores
//   S5: hA(t+1) finish: all 512 threads, one (j,s) each
// ---------------------------------------------------------------------------
__global__ void __launch_bounds__(THREADS, 1)
hyd_kernel(const float* __restrict__ hyd,
           const float* __restrict__ W0, const float* __restrict__ b0,
           const float* __restrict__ W1, const float* __restrict__ b1,
           const float* __restrict__ Wi, const float* __restrict__ bi,
           const float* __restrict__ Wo, const float* __restrict__ bo,
           float* __restrict__ out)
{
    __shared__ Smem S;
    const int tid   = threadIdx.x;
    const int j     = tid & 127;
    const int q     = tid >> 7;
    const int lane  = tid & 31;
    const int wwarp = tid >> 5;         // 0..15
    const int blk   = blockIdx.x;

    // ---- register-resident weight slices ----
    float w1r[32], wcr[32];
    #pragma unroll
    for (int k = 0; k < 32; k++) w1r[k] = W1[j * 128 + q * 32 + k];
    if (j < 9) {
        #pragma unroll
        for (int k = 0; k < 32; k++) wcr[k] = Wi[j * 128 + q * 32 + k];
    } else if (j < 89) {
        #pragma unroll
        for (int k = 0; k < 32; k++) wcr[k] = Wo[(j - 9) * 128 + q * 32 + k];
    } else {
        #pragma unroll
        for (int k = 0; k < 32; k++) wcr[k] = 0.f;
    }

    // ---- SMEM init ----
    for (int idx = tid; idx < 16 * 128; idx += THREADS) {
        int i = idx >> 7, jj = idx & 127;
        S.w0t[idx] = W0[jj * 24 + i];
    }
    for (int idx = tid; idx < 8 * 128; idx += THREADS) {
        int k = idx >> 7, jj = idx & 127;
        S.w0sp[idx] = 0.01f * W0[jj * 24 + 16 + k];
    }
    if (tid < 128) { S.b0s[tid] = b0[tid]; S.b1s[tid] = b1[tid]; }
    if (tid < 89)  S.bcs[tid] = (tid < 9) ? bi[tid] : bo[tid - 9];
    if (tid < 32)  S.st[tid] = ((tid & 7) == 1) ? 1.0f : 0.0f;
    if (tid < SPB) S.bflow_s[tid] = g_baseflow[blk * SPB + tid];

    // per-warp roles
    const int bsample = blk * SPB + wwarp;          // warps 0-3: epilogue sample
    const int xsample = blk * SPB + (wwarp - 4);    // warps 4-7: x prefetch
    float rain_cur = 0.f, rain_next = 0.f, xreg = 0.f;

    if (wwarp < 4 && lane == 0)
        rain_cur = hyd[bsample * 17 + 1];           // x_0[rain]
    if (wwarp >= 4 && wwarp < 8 && lane < 16)
        S.xin[lane * 4 + (wwarp - 4)] = hyd[xsample * 17 + 1 + lane];  // x_0
    __syncthreads();

    // ---- bootstrap: l0x(0) ----
    if ((wwarp & 3) == 3) {
        int jj = (tid >> 7) * 32 + lane;
        float bj = S.b0s[jj];
        u64 a01 = pack2(bj, bj), a23 = a01;
        #pragma unroll
        for (int i = 0; i < 16; i++) {
            float w = S.w0t[i * 128 + jj];
            u64 wd = pack2(w, w);
            ulonglong2 h = *(const ulonglong2*)&S.xin[i * 4];
            fma2(a01, h.x, wd); fma2(a23, h.y, wd);
        }
        ulonglong2 pv; pv.x = a01; pv.y = a23;
        *(ulonglong2*)&S.l0p[jj * 4] = pv;
    }
    __syncthreads();

    // ---- bootstrap: hA(0) ----
    {
        int jj = tid >> 2, s = tid & 3;
        float v = S.l0p[jj * 4 + s];
        #pragma unroll
        for (int k = 0; k < 8; k++)
            v = fmaf(S.w0sp[k * 128 + jj], S.st[s * 8 + k], v);
        S.hA[jj * 4 + s] = fmaxf(v, 0.f);
    }
    __syncthreads();

    // persistent stores in lane 0 of warps 0-3
    float sv[8];
    #pragma unroll
    for (int k = 0; k < 8; k++) sv[k] = (k == 1) ? 1.0f : 0.0f;

    for (int t = 0; t < STEPS; t++) {
        // ======== S1: layer1 partials ========
        {
            float bj = (q == 0) ? S.b1s[j] : 0.f;
            u64 a01 = pack2(bj, bj), a23 = a01;
            const float* hp = &S.hA[q * 128];
            #pragma unroll
            for (int k = 0; k < 32; k++) {
                u64 wd = pack2(w1r[k], w1r[k]);
                ulonglong2 h = *(const ulonglong2*)&hp[k * 4];
                fma2(a01, h.x, wd); fma2(a23, h.y, wd);
            }
            ulonglong2 pv; pv.x = a01; pv.y = a23;
            *(ulonglong2*)&S.part[q][j][0] = pv;
        }
        // prefetch x_{t+1} / rain_{t+1}
        if (t + 1 < STEPS) {
            if (wwarp < 4 && lane == 0)
                rain_next = hyd[((t + 1) * BATCH + bsample) * 17 + 1];
            if (wwarp >= 4 && wwarp < 8 && lane < 16)
                xreg = hyd[((t + 1) * BATCH + xsample) * 17 + 1 + lane];
        }
        __syncthreads();

        // ======== S2: combine1 -> hB ; stage x_{t+1} ========
        {
            int jj = tid >> 2, s = tid & 3;
            float v = S.part[0][jj][s] + S.part[1][jj][s]
                    + S.part[2][jj][s] + S.part[3][jj][s];
            S.hB[jj * 4 + s] = fmaxf(v, 0.f);
        }
        if (wwarp >= 4 && wwarp < 8 && lane < 16)
            S.xin[lane * 4 + (wwarp - 4)] = xreg;
        __syncthreads();

        // ======== S3: layer2 partials || l0x(t+1) ========
        if ((wwarp & 3) == 3) {
            int jj = (tid >> 7) * 32 + lane;
            float bj = S.b0s[jj];
            u64 a01 = pack2(bj, bj), a23 = a01;
            #pragma unroll
            for (int i = 0; i < 16; i++) {
                float w = S.w0t[i * 128 + jj];
                u64 wd = pack2(w, w);
                ulonglong2 h = *(const ulonglong2*)&S.xin[i * 4];
                fma2(a01, h.x, wd); fma2(a23, h.y, wd);
            }
            ulonglong2 pv; pv.x = a01; pv.y = a23;
            *(ulonglong2*)&S.l0p[jj * 4] = pv;
        } else if (j < 89) {
            float bj = (q == 0) ? S.bcs[j] : 0.f;
            u64 a01 = pack2(bj, bj), a23 = a01;
            const float* hp = &S.hB[q * 128];
            #pragma unroll
            for (int k = 0; k < 32; k++) {
                u64 wd = pack2(wcr[k], wcr[k]);
                ulonglong2 h = *(const ulonglong2*)&hp[k * 4];
                fma2(a01, h.x, wd); fma2(a23, h.y, wd);
            }
            ulonglong2 pv; pv.x = a01; pv.y = a23;
            *(ulonglong2*)&S.part[q][j][0] = pv;
        }
        __syncthreads();

        // ======== S4: epilogue (warps 0-3, warp s = sample s) ========
        if (wwarp < 4) {
            const int s = wwarp;
            // combine2 for this sample: lane covers j = lane, lane+32, lane+64
            float v0 = S.part[0][lane][s] + S.part[1][lane][s]
                     + S.part[2][lane][s] + S.part[3][lane][s];
            int j1 = lane + 32, j2 = lane + 64;
            float v1 = S.part[0][j1][s] + S.part[1][j1][s]
                     + S.part[2][j1][s] + S.part[3][j1][s];
            float v2 = 0.f;
            if (lane < 25)
                v2 = S.part[0][j2][s] + S.part[1][j2][s]
                   + S.part[2][j2][s] + S.part[3][j2][s];

            // sigmoids spread across lanes (<=6 MUFU warp-instrs)
            if (lane >= 9) S.outg[s][lane - 9] = fast_sigmoid(v0);
            S.outg[s][lane + 23] = fast_sigmoid(v1);
            if (lane < 25) S.outg[s][lane + 55] = fast_sigmoid(v2);

            // gather the 9 logits into registers of every lane (cheap, indep)
            float lg[9];
            #pragma unroll
            for (int k = 0; k < 9; k++)
                lg[k] = __shfl_sync(0xffffffffu, v0, k);
            __syncwarp();

            if (lane == 0) {
                // scalar softmax (register-resident, no reduction trees)
                float m = lg[0];
                #pragma unroll
                for (int k = 1; k < 9; k++) m = fmaxf(m, lg[k]);
                float e[9], ssum = 0.f;
                #pragma unroll
                for (int k = 0; k < 9; k++) { e[k] = __expf(lg[k] - m); ssum += e[k]; }
                float r2 = __fdividef(rain_cur, ssum);
                #pragma unroll
                for (int k = 0; k < 8; k++) sv[k] += e[k + 1] * r2;

                const float* bb = S.outg[s];
                #pragma unroll
                for (int d = 0; d < 8; d++) {
                    float fb[8]; float fsum = 0.f;
                    #pragma unroll
                    for (int k = 0; k < 8; k++) { fb[k] = bb[d * 8 + k] * sv[k]; fsum += fb[k]; }
                    #pragma unroll
                    for (int k = 0; k < 8; k++) sv[k] -= fb[k];
                    sv[d] += fsum;
                }
                #pragma unroll
                for (int k = 0; k < 8; k++) sv[k] -= bb[64 + k] * sv[k];   // escape
                float flow = 0.f;
                #pragma unroll
                for (int k = 0; k < 8; k++) {
                    float fd = bb[72 + k] * sv[k];
                    flow += fd;
                    sv[k] -= fd;
                }
                out[t * BATCH + bsample] = flow;
                if (t == 0)
                    sv[2] = S.bflow_s[s] / fmaxf(bb[74], 1e-5f);   // b_flow[SLOW]
                #pragma unroll
                for (int k = 0; k < 8; k++) S.st[s * 8 + k] = sv[k];
                rain_cur = rain_next;
            }
        }
        __syncthreads();

        // ======== S5: hA(t+1) finish (all 512 threads, one (j,s) each) ====
        {
            int jj = tid >> 2, s = tid & 3;
            float v = S.l0p[jj * 4 + s];
            #pragma unroll
            for (int k = 0; k < 8; k++)
                v = fmaf(S.w0sp[k * 128 + jj], S.st[s * 8 + k], v);
            S.hA[jj * 4 + s] = fmaxf(v, 0.f);
        }
        __syncthreads();
    }
}

// ---------------------------------------------------------------------------
// Harness entry.  Inputs: hyd_input, W0, b0, W1, b1, W_in, b_in, W_out, b_out
// ---------------------------------------------------------------------------
extern "C" void kernel_launch(void* const* d_in, const int* in_sizes, int n_in,
                              void* d_out, int out_size) {
    const float* hyd = (const float*)d_in[0];
    const float* W0  = (const float*)d_in[1];
    const float* b0  = (const float*)d_in[2];
    const float* W1  = (const float*)d_in[3];
    const float* b1  = (const float*)d_in[4];
    const float* Wi  = (const float*)d_in[5];
    const float* bi  = (const float*)d_in[6];
    const float* Wo  = (const float*)d_in[7];
    const float* bo  = (const float*)d_in[8];
    float* out = (float*)d_out;

    baseflow_kernel<<<BATCH, 1024>>>(hyd);
    hyd_kernel<<<NBLK, THREADS>>>(hyd, W0, b0, W1, b1, Wi, bi, Wo, bo, out);
}